// round 2
// baseline (speedup 1.0000x reference)
#include <cuda_runtime.h>
#include <math.h>

// router: per-token top2-softmax + soft-softmax blended 4-way combine.
// N = 32768 tokens, D = 512, K = 4.
// R2: occupancy-focused rewrite. 4 tokens/warp, x reloaded from L1 for the
// combine (frees ~120 regs), 256 thr/CTA, 3 CTAs/SM.

#define THREADS 256
#define WPB 8            // warps per block
#define D_DIM 512
#define SMEM_FLOATS 16384  // W_top (4x2048) + W_soft (4x2048)
#define TPW 4            // tokens per warp

__device__ __forceinline__ void compute_w(const float lt_in[4], const float ls_in[4],
                                          const float bt[4], const float bs[4],
                                          float a, float w[4]) {
    float t[4], s[4];
#pragma unroll
    for (int k = 0; k < 4; k++) { t[k] = lt_in[k] + bt[k]; s[k] = ls_in[k] + bs[k]; }

    // soft = softmax(s)
    float mx = fmaxf(fmaxf(s[0], s[1]), fmaxf(s[2], s[3]));
    float e[4], sum = 0.f;
#pragma unroll
    for (int k = 0; k < 4; k++) { e[k] = __expf(s[k] - mx); sum += e[k]; }
    float inv = 1.f / sum;

    // top-2 of t (first occurrence on ties, matching jax top_k)
    int i1 = 0; float v1 = t[0];
#pragma unroll
    for (int k = 1; k < 4; k++) { if (t[k] > v1) { v1 = t[k]; i1 = k; } }
    int i2 = -1; float v2 = -3.402823466e38f;
#pragma unroll
    for (int k = 0; k < 4; k++) { if (k != i1 && t[k] > v2) { v2 = t[k]; i2 = k; } }

    float e2 = __expf(v2 - v1);        // v2 <= v1, e2 in (0,1]
    float d  = 1.f / (1.f + e2);
    float p1 = d;
    float p2 = e2 * d;

#pragma unroll
    for (int k = 0; k < 4; k++) {
        float hard = (k == i1) ? p1 : ((k == i2) ? p2 : 0.f);
        w[k] = a * hard + (1.f - a) * e[k] * inv;
    }
}

__global__ void __launch_bounds__(THREADS, 3)
router_kernel(const float* __restrict__ m0, const float* __restrict__ m1,
              const float* __restrict__ m2, const float* __restrict__ m3,
              const float* __restrict__ Wt, const float* __restrict__ bt,
              const float* __restrict__ Ws, const float* __restrict__ bs,
              const float* __restrict__ alpha,
              float* __restrict__ out, int n_tokens)
{
    extern __shared__ float sW[];   // [0:8192) = W_top rows, [8192:16384) = W_soft rows

    // Stage W into shared (vectorized, once per block)
    {
        const float4* gt = (const float4*)Wt;
        const float4* gs = (const float4*)Ws;
        float4* st = (float4*)sW;
        float4* ss = (float4*)(sW + 8192);
        for (int i = threadIdx.x; i < 2048; i += THREADS) {
            st[i] = gt[i];
            ss[i] = gs[i];
        }
    }
    __syncthreads();

    const int lane = threadIdx.x & 31;
    const int warp = threadIdx.x >> 5;
    const int warps_total = gridDim.x * WPB;
    const int n_groups = n_tokens >> 2;   // 4 tokens per group

    const float a = 1.f / (1.f + __expf(-alpha[0]));
    float bt_r[4], bs_r[4];
#pragma unroll
    for (int k = 0; k < 4; k++) { bt_r[k] = __ldg(bt + k); bs_r[k] = __ldg(bs + k); }

    for (int g = blockIdx.x * WPB + warp; g < n_groups; g += warps_total) {
        const int base = g * (TPW * D_DIM) + lane;

        // ---- Matvec: 8 rows x 4 tokens, x streamed (not retained) ----
        float at[TPW][4] = {{0}}, as_[TPW][4] = {{0}};
#pragma unroll 4
        for (int m = 0; m < 16; m++) {
            const int off = base + 32 * m;
            float x[4][TPW];
#pragma unroll
            for (int t = 0; t < TPW; t++) {
                const int o = off + t * D_DIM;
                x[0][t] = __ldg(m0 + o); x[1][t] = __ldg(m1 + o);
                x[2][t] = __ldg(m2 + o); x[3][t] = __ldg(m3 + o);
            }
            const int jb = (lane + 32 * m) << 2;  // element idx into a 2048-wide row
#pragma unroll
            for (int r = 0; r < 4; r++) {
                const float4 wt = *(const float4*)&sW[r * 2048 + jb];
                const float4 ws = *(const float4*)&sW[8192 + r * 2048 + jb];
#pragma unroll
                for (int t = 0; t < TPW; t++) {
                    at[t][r]  += x[0][t] * wt.x + x[1][t] * wt.y + x[2][t] * wt.z + x[3][t] * wt.w;
                    as_[t][r] += x[0][t] * ws.x + x[1][t] * ws.y + x[2][t] * ws.z + x[3][t] * ws.w;
                }
            }
        }

        // ---- Butterfly reduction across 32 lanes ----
#pragma unroll
        for (int o = 16; o > 0; o >>= 1) {
#pragma unroll
            for (int t = 0; t < TPW; t++)
#pragma unroll
                for (int r = 0; r < 4; r++) {
                    at[t][r]  += __shfl_xor_sync(0xffffffffu, at[t][r],  o);
                    as_[t][r] += __shfl_xor_sync(0xffffffffu, as_[t][r], o);
                }
        }

        // ---- Routing weights (redundant per lane; cheap) ----
        float w[TPW][4];
#pragma unroll
        for (int t = 0; t < TPW; t++) compute_w(at[t], as_[t], bt_r, bs_r, a, w[t]);

        // ---- Combine: reload x (L1 hits — lines just fetched), coalesced store ----
#pragma unroll 4
        for (int m = 0; m < 16; m++) {
            const int off = base + 32 * m;
#pragma unroll
            for (int t = 0; t < TPW; t++) {
                const int o = off + t * D_DIM;
                out[o] = __ldg(m0 + o) * w[t][0] + __ldg(m1 + o) * w[t][1]
                       + __ldg(m2 + o) * w[t][2] + __ldg(m3 + o) * w[t][3];
            }
        }
    }
}

extern "C" void kernel_launch(void* const* d_in, const int* in_sizes, int n_in,
                              void* d_out, int out_size) {
    const float* m0    = (const float*)d_in[0];
    const float* m1    = (const float*)d_in[1];
    const float* m2    = (const float*)d_in[2];
    const float* m3    = (const float*)d_in[3];
    const float* Wt    = (const float*)d_in[4];
    const float* bt    = (const float*)d_in[5];
    const float* Ws    = (const float*)d_in[6];
    const float* bs    = (const float*)d_in[7];
    const float* alpha = (const float*)d_in[8];
    float* out = (float*)d_out;

    const int n_tokens = in_sizes[0] / D_DIM;  // 32768

    cudaFuncSetAttribute(router_kernel,
                         cudaFuncAttributeMaxDynamicSharedMemorySize,
                         SMEM_FLOATS * (int)sizeof(float));

    int blocks = 3 * 148;   // 3 CTAs/SM
    const int n_groups = n_tokens >> 2;
    if (blocks * WPB > n_groups) blocks = (n_groups + WPB - 1) / WPB;

    router_kernel<<<blocks, THREADS, SMEM_FLOATS * sizeof(float)>>>(
        m0, m1, m2, m3, Wt, bt, Ws, bs, alpha, out, n_tokens);
}

// round 5
// speedup vs baseline: 1.4145x; 1.4145x over previous
#include <cuda_runtime.h>
#include <math.h>

// router: per-token top2-softmax + soft-softmax blended 4-way combine.
// N = 32768 tokens, D = 512, K = 4.
// R3: TPW=2 streamed-x with L2-resident reload (window 57MB < 126MB L2),
// float4 LDG/STG, __ldcs/__stcs on the second pass, transposed conflict-free
// W layout in smem, 256thr x 3 CTAs/SM.

#define THREADS 256
#define WPB 8              // warps per block
#define D_DIM 512
#define DV 128             // D in float4 units
#define SMEM_FLOATS 16384  // W_top (4x2048) + W_soft (4x2048)

__device__ __forceinline__ float comp(const float4 v, int i) {
    return i == 0 ? v.x : (i == 1 ? v.y : (i == 2 ? v.z : v.w));
}

__device__ __forceinline__ void compute_w(const float lt_in[4], const float ls_in[4],
                                          const float bt[4], const float bs[4],
                                          float a, float w[4]) {
    float t[4], s[4];
#pragma unroll
    for (int k = 0; k < 4; k++) { t[k] = lt_in[k] + bt[k]; s[k] = ls_in[k] + bs[k]; }

    // soft = softmax(s)
    float mx = fmaxf(fmaxf(s[0], s[1]), fmaxf(s[2], s[3]));
    float e[4], sum = 0.f;
#pragma unroll
    for (int k = 0; k < 4; k++) { e[k] = __expf(s[k] - mx); sum += e[k]; }
    float inv = 1.f / sum;

    // top-2 of t (first occurrence on ties, matching jax top_k)
    int i1 = 0; float v1 = t[0];
#pragma unroll
    for (int k = 1; k < 4; k++) { if (t[k] > v1) { v1 = t[k]; i1 = k; } }
    int i2 = -1; float v2 = -3.402823466e38f;
#pragma unroll
    for (int k = 0; k < 4; k++) { if (k != i1 && t[k] > v2) { v2 = t[k]; i2 = k; } }

    float e2 = __expf(v2 - v1);   // v2 <= v1
    float d  = 1.f / (1.f + e2);
    float p1 = d;
    float p2 = e2 * d;

#pragma unroll
    for (int k = 0; k < 4; k++) {
        float hard = (k == i1) ? p1 : ((k == i2) ? p2 : 0.f);
        w[k] = a * hard + (1.f - a) * e[k] * inv;
    }
}

__global__ void __launch_bounds__(THREADS, 3)
router_kernel(const float* __restrict__ m0, const float* __restrict__ m1,
              const float* __restrict__ m2, const float* __restrict__ m3,
              const float* __restrict__ Wt, const float* __restrict__ bt,
              const float* __restrict__ Ws, const float* __restrict__ bs,
              const float* __restrict__ alpha,
              float* __restrict__ out, int n_tokens)
{
    extern __shared__ float4 sW4[];   // 8 rows x 512 float4, transposed layout

    // Stage W transposed: float4 #d of row r stored at slot l + 32*(4j+i),
    // where d = 4l + 128j + i. Lane l then reads consecutive 16B across the
    // warp for every (j,i) -> conflict-free LDS.128.
    {
        const float4* gt = (const float4*)Wt;   // 4 rows x 512 float4
        const float4* gs = (const float4*)Ws;
        for (int idx = threadIdx.x; idx < 4096; idx += THREADS) {
            int row = idx >> 9;        // 0..7 (0-3 top, 4-7 soft)
            int d   = idx & 511;
            int l   = (d >> 2) & 31;
            int j   = d >> 7;
            int i   = d & 3;
            int slot = l + 32 * (4 * j + i);
            float4 v = (row < 4) ? gt[row * 512 + d] : gs[(row - 4) * 512 + d];
            sW4[row * 512 + slot] = v;
        }
    }
    __syncthreads();

    const int lane = threadIdx.x & 31;
    const int warp = threadIdx.x >> 5;
    const int warps_total = gridDim.x * WPB;
    const int n_pairs = n_tokens >> 1;

    const float a = 1.f / (1.f + __expf(-alpha[0]));
    float bt_r[4], bs_r[4];
#pragma unroll
    for (int k = 0; k < 4; k++) { bt_r[k] = __ldg(bt + k); bs_r[k] = __ldg(bs + k); }

    const float4* m0v = (const float4*)m0;
    const float4* m1v = (const float4*)m1;
    const float4* m2v = (const float4*)m2;
    const float4* m3v = (const float4*)m3;
    float4* outv = (float4*)out;

    for (int g = blockIdx.x * WPB + warp; g < n_pairs; g += warps_total) {
        const int b0 = g * (2 * DV) + lane;  // token0 float4 base
        const int b1 = b0 + DV;              // token1

        float at[2][4] = {{0}}, as_[2][4] = {{0}};

#pragma unroll
        for (int j = 0; j < 4; j++) {
            // x for this j-chunk: 8 x LDG.128 (first pass: cache normally)
            float4 xa0 = __ldg(m0v + b0 + 32 * j), xa1 = __ldg(m1v + b0 + 32 * j);
            float4 xa2 = __ldg(m2v + b0 + 32 * j), xa3 = __ldg(m3v + b0 + 32 * j);
            float4 xb0 = __ldg(m0v + b1 + 32 * j), xb1 = __ldg(m1v + b1 + 32 * j);
            float4 xb2 = __ldg(m2v + b1 + 32 * j), xb3 = __ldg(m3v + b1 + 32 * j);
#pragma unroll
            for (int i = 0; i < 4; i++) {
                const int slot = lane + 32 * (4 * j + i);
                const float A0 = comp(xa0, i), A1 = comp(xa1, i), A2 = comp(xa2, i), A3 = comp(xa3, i);
                const float B0 = comp(xb0, i), B1 = comp(xb1, i), B2 = comp(xb2, i), B3 = comp(xb3, i);
#pragma unroll
                for (int r = 0; r < 4; r++) {
                    const float4 wt = sW4[r * 512 + slot];
                    const float4 ws = sW4[(4 + r) * 512 + slot];
                    at[0][r]  += A0 * wt.x + A1 * wt.y + A2 * wt.z + A3 * wt.w;
                    at[1][r]  += B0 * wt.x + B1 * wt.y + B2 * wt.z + B3 * wt.w;
                    as_[0][r] += A0 * ws.x + A1 * ws.y + A2 * ws.z + A3 * ws.w;
                    as_[1][r] += B0 * ws.x + B1 * ws.y + B2 * ws.z + B3 * ws.w;
                }
            }
        }

        // ---- Butterfly reduction across 32 lanes ----
#pragma unroll
        for (int o = 16; o > 0; o >>= 1) {
#pragma unroll
            for (int t = 0; t < 2; t++)
#pragma unroll
                for (int r = 0; r < 4; r++) {
                    at[t][r]  += __shfl_xor_sync(0xffffffffu, at[t][r],  o);
                    as_[t][r] += __shfl_xor_sync(0xffffffffu, as_[t][r], o);
                }
        }

        // ---- Routing weights (redundant per lane; cheap) ----
        float w0[4], w1[4];
        compute_w(at[0], as_[0], bt_r, bs_r, a, w0);
        compute_w(at[1], as_[1], bt_r, bs_r, a, w1);

        // ---- Combine: reload x from L2 (__ldcs: last use), stream stores ----
#pragma unroll
        for (int j = 0; j < 4; j++) {
            {
                const int o = b0 + 32 * j;
                float4 x0 = __ldcs(m0v + o), x1 = __ldcs(m1v + o);
                float4 x2 = __ldcs(m2v + o), x3 = __ldcs(m3v + o);
                float4 r;
                r.x = x0.x * w0[0] + x1.x * w0[1] + x2.x * w0[2] + x3.x * w0[3];
                r.y = x0.y * w0[0] + x1.y * w0[1] + x2.y * w0[2] + x3.y * w0[3];
                r.z = x0.z * w0[0] + x1.z * w0[1] + x2.z * w0[2] + x3.z * w0[3];
                r.w = x0.w * w0[0] + x1.w * w0[1] + x2.w * w0[2] + x3.w * w0[3];
                __stcs(outv + o, r);
            }
            {
                const int o = b1 + 32 * j;
                float4 x0 = __ldcs(m0v + o), x1 = __ldcs(m1v + o);
                float4 x2 = __ldcs(m2v + o), x3 = __ldcs(m3v + o);
                float4 r;
                r.x = x0.x * w1[0] + x1.x * w1[1] + x2.x * w1[2] + x3.x * w1[3];
                r.y = x0.y * w1[0] + x1.y * w1[1] + x2.y * w1[2] + x3.y * w1[3];
                r.z = x0.z * w1[0] + x1.z * w1[1] + x2.z * w1[2] + x3.z * w1[3];
                r.w = x0.w * w1[0] + x1.w * w1[1] + x2.w * w1[2] + x3.w * w1[3];
                __stcs(outv + o, r);
            }
        }
    }
}

extern "C" void kernel_launch(void* const* d_in, const int* in_sizes, int n_in,
                              void* d_out, int out_size) {
    const float* m0    = (const float*)d_in[0];
    const float* m1    = (const float*)d_in[1];
    const float* m2    = (const float*)d_in[2];
    const float* m3    = (const float*)d_in[3];
    const float* Wt    = (const float*)d_in[4];
    const float* bt    = (const float*)d_in[5];
    const float* Ws    = (const float*)d_in[6];
    const float* bs    = (const float*)d_in[7];
    const float* alpha = (const float*)d_in[8];
    float* out = (float*)d_out;

    const int n_tokens = in_sizes[0] / D_DIM;  // 32768

    cudaFuncSetAttribute(router_kernel,
                         cudaFuncAttributeMaxDynamicSharedMemorySize,
                         SMEM_FLOATS * (int)sizeof(float));

    int blocks = 3 * 148;   // 3 CTAs/SM
    const int n_pairs = n_tokens >> 1;
    if (blocks * WPB > n_pairs) blocks = (n_pairs + WPB - 1) / WPB;

    router_kernel<<<blocks, THREADS, SMEM_FLOATS * sizeof(float)>>>(
        m0, m1, m2, m3, Wt, bt, Ws, bs, alpha, out, n_tokens);
}